// round 5
// baseline (speedup 1.0000x reference)
#include <cuda_runtime.h>

// SVConvTranspose2d, round 5: scatter-in-w — aligned float4 loads for BOTH
// weight and x, kw shift absorbed into an 8-wide accumulator window,
// cross-lane combine via 4 shuffles per batch at the very end.
//
// x:      (4, 16, 128, 128) f32        -- 4 MB, L2-hot
// weight: (16, 16, 5, 5, 128, 128) f32 -- 419 MB, read EXACTLY once, LDG.128
// bias:   (1, 16, 1, 1) f32
// out:    (4, 16, 128, 128) f32
//
// out[n,o,oh,ow] = bias[o] + sum wt[i,o,kh,kw,h,w] * x[n,i,h,w],
//   h = oh+2-kh (gather), ow = w+kw-2 (scatter).
//
// Thread owns input quad w in [4q,4q+4) and an output window [4q-2,4q+6):
//   acc[n][k] ~ out position 4q-2+k;  tap (kw,j) -> k = j+kw.  No masks,
// no shuffles in the loop.  Final combine per n:
//   out[m] = acc[m+2] + shfl_up(acc[m+6])   (m=0,1; zero at lane 0)
//          = acc[m+2] + shfl_down(acc[m-2]) (m=2,3; zero at lane 31)
//
// Block = 256 thr = (ih:4 i-slices of 4) x (o2:2 outs) x (q:32 quads).
// Grid  = 128 rows x 8 o-pairs = 1024 blocks. Smem reduces the 4 i-slices.

#define H_  128
#define W_  128
#define HW  16384

__global__ __launch_bounds__(256, 4)
void svct_kernel(const float* __restrict__ x,
                 const float* __restrict__ wt,
                 const float* __restrict__ bias,
                 float* __restrict__ out)
{
    __shared__ float red[2][4][4][W_];   // [o2][n][ih][w]  16 KB

    const int t   = threadIdx.x;
    const int q   = t & 31;              // quad index in row
    const int o2  = (t >> 5) & 1;        // which of the 2 outs
    const int ih  = t >> 6;              // i-slice 0..3
    const int oh  = blockIdx.x >> 3;     // output row
    const int og  = blockIdx.x & 7;      // o-pair
    const int oc  = og * 2 + o2;         // output channel
    const int ibase = ih * 4;

    float acc[4][8];                     // [n][window k]
    #pragma unroll
    for (int n = 0; n < 4; n++)
        #pragma unroll
        for (int k = 0; k < 8; k++)
            acc[n][k] = 0.0f;

    #pragma unroll 1
    for (int kh = 0; kh < 5; kh++) {
        const int h = oh + 2 - kh;
        if ((unsigned)h >= (unsigned)H_) continue;

        #pragma unroll 1
        for (int ii = 0; ii < 4; ii++) {
            const int i = ibase + ii;

            // 5 aligned weight quads (the read-once 419MB stream)
            const long wrow = ((long)((i * 16 + oc) * 5 + kh) * 5) * HW + (long)h * W_;
            float4 w4[5];
            #pragma unroll
            for (int kw = 0; kw < 5; kw++)
                w4[kw] = __ldcs((const float4*)(wt + wrow + (long)kw * HW) + q);

            // 4 aligned x quads (L1/L2-hot), same spatial position
            float4 xq[4];
            #pragma unroll
            for (int n = 0; n < 4; n++)
                xq[n] = __ldg((const float4*)x + ((n * 16 + i) * H_ + h) * 32 + q);

            #pragma unroll
            for (int kw = 0; kw < 5; kw++) {
                const float wv[4] = {w4[kw].x, w4[kw].y, w4[kw].z, w4[kw].w};
                #pragma unroll
                for (int n = 0; n < 4; n++) {
                    const float xv[4] = {xq[n].x, xq[n].y, xq[n].z, xq[n].w};
                    #pragma unroll
                    for (int j = 0; j < 4; j++)
                        acc[n][j + kw] = fmaf(wv[j], xv[j], acc[n][j + kw]);
                }
            }
        }
    }

    // cross-lane combine (4 shuffles per n), then smem-reduce the i-slices
    const bool q0  = (q == 0);
    const bool q31 = (q == 31);
    #pragma unroll
    for (int n = 0; n < 4; n++) {
        float up6 = __shfl_up_sync(0xffffffffu, acc[n][6], 1);
        float up7 = __shfl_up_sync(0xffffffffu, acc[n][7], 1);
        float dn0 = __shfl_down_sync(0xffffffffu, acc[n][0], 1);
        float dn1 = __shfl_down_sync(0xffffffffu, acc[n][1], 1);
        if (q0)  { up6 = 0.0f; up7 = 0.0f; }
        if (q31) { dn0 = 0.0f; dn1 = 0.0f; }
        *(float4*)&red[o2][n][ih][4 * q] =
            make_float4(acc[n][2] + up6, acc[n][3] + up7,
                        acc[n][4] + dn0, acc[n][5] + dn1);
    }
    __syncthreads();

    // 256 writer threads: (o2w:2) x (nw:4) x (qw:32)
    const int o2w = t >> 7;
    const int nw  = (t >> 5) & 3;
    const int qw  = t & 31;
    const int ocw = og * 2 + o2w;

    float4 s0 = *(const float4*)&red[o2w][nw][0][4 * qw];
    float4 s1 = *(const float4*)&red[o2w][nw][1][4 * qw];
    float4 s2 = *(const float4*)&red[o2w][nw][2][4 * qw];
    float4 s3 = *(const float4*)&red[o2w][nw][3][4 * qw];

    const float b = __ldg(bias + ocw);
    float4 r;
    r.x = s0.x + s1.x + s2.x + s3.x + b;
    r.y = s0.y + s1.y + s2.y + s3.y + b;
    r.z = s0.z + s1.z + s2.z + s3.z + b;
    r.w = s0.w + s1.w + s2.w + s3.w + b;

    ((float4*)out)[((nw * 16 + ocw) * H_ + oh) * 32 + qw] = r;
}

extern "C" void kernel_launch(void* const* d_in, const int* in_sizes, int n_in,
                              void* d_out, int out_size)
{
    const float* x    = (const float*)d_in[0];
    const float* wt   = (const float*)d_in[1];
    const float* bias = (const float*)d_in[2];
    float*       out  = (float*)d_out;

    svct_kernel<<<1024, 256>>>(x, wt, bias, out);
}